// round 7
// baseline (speedup 1.0000x reference)
#include <cuda_runtime.h>
#include <cstdint>

// Problem constants
#define T_TOK 4096
#define DIM   1024
#define HID   5632
#define EACT  4
#define TB    1024   // token tile for scratch reuse

// Scratch: combine weights + intermediate G (tf32 bits), one token-block (23 MB)
__device__ float g_cw[T_TOK * EACT];
__device__ __align__(16) uint32_t g_G[(size_t)TB * HID];

__device__ __forceinline__ uint32_t f2tf32(float f) {
    uint32_t r;
    asm("cvt.rna.tf32.f32 %0, %1;" : "=r"(r) : "f"(f));
    return r;
}
__device__ __forceinline__ uint32_t b2tf32(uint32_t b) {
    return f2tf32(__uint_as_float(b));
}

__device__ __forceinline__ void cp16(uint32_t* smem_ptr, const void* gptr) {
    uint32_t a = (uint32_t)__cvta_generic_to_shared(smem_ptr);
    asm volatile("cp.async.cg.shared.global [%0], [%1], 16;" :: "r"(a), "l"(gptr));
}
#define CP_COMMIT() asm volatile("cp.async.commit_group;")
#define CP_WAIT0()  asm volatile("cp.async.wait_group 0;")

__device__ __forceinline__ void mma8(float* c,
                                     uint32_t a0, uint32_t a1, uint32_t a2, uint32_t a3,
                                     uint32_t b0, uint32_t b1) {
    asm volatile(
        "mma.sync.aligned.m16n8k8.row.col.f32.tf32.tf32.f32 "
        "{%0,%1,%2,%3}, {%4,%5,%6,%7}, {%8,%9}, {%0,%1,%2,%3};\n"
        : "+f"(c[0]), "+f"(c[1]), "+f"(c[2]), "+f"(c[3])
        : "r"(a0), "r"(a1), "r"(a2), "r"(a3), "r"(b0), "r"(b1));
}

__device__ __forceinline__ float silu_f(float v) {
    return v / (1.0f + __expf(-v));
}

// ---------------------------------------------------------------------------
// Gate: one warp per token; experts 4..7 masked. softmax->top2->renorm ==
// softmax over the two best logits.
// ---------------------------------------------------------------------------
__global__ void gate_kernel(const float* __restrict__ x,
                            const float* __restrict__ gw) {
    int warp = (blockIdx.x * blockDim.x + threadIdx.x) >> 5;
    int lane = threadIdx.x & 31;
    if (warp >= T_TOK) return;

    const float* xr = x + (size_t)warp * DIM;
    float p0 = 0.f, p1 = 0.f, p2 = 0.f, p3 = 0.f;
    for (int d = lane; d < DIM; d += 32) {
        float xv = xr[d];
        p0 += xv * gw[0 * DIM + d];
        p1 += xv * gw[1 * DIM + d];
        p2 += xv * gw[2 * DIM + d];
        p3 += xv * gw[3 * DIM + d];
    }
    #pragma unroll
    for (int off = 16; off; off >>= 1) {
        p0 += __shfl_down_sync(0xffffffff, p0, off);
        p1 += __shfl_down_sync(0xffffffff, p1, off);
        p2 += __shfl_down_sync(0xffffffff, p2, off);
        p3 += __shfl_down_sync(0xffffffff, p3, off);
    }
    if (lane == 0) {
        float l[4] = {p0, p1, p2, p3};
        int i0 = 0;
        #pragma unroll
        for (int e = 1; e < 4; e++) if (l[e] > l[i0]) i0 = e;
        int i1 = -1;
        #pragma unroll
        for (int e = 0; e < 4; e++) {
            if (e == i0) continue;
            if (i1 < 0 || l[e] > l[i1]) i1 = e;
        }
        float w0 = 1.0f / (1.0f + __expf(l[i1] - l[i0]));
        float w1 = 1.0f - w0;
        float* cwr = g_cw + warp * 4;
        cwr[0] = 0.f; cwr[1] = 0.f; cwr[2] = 0.f; cwr[3] = 0.f;
        cwr[i0] = w0;
        cwr[i1] = w1;
    }
}

// ---------------------------------------------------------------------------
// GEMM13: G[t,h] = tf32( cw[t,e] * silu(X@W1)[t,h] * (X@W3)[t,h] )
// BM=128, BN=64, BK=32; 256 thr. A via cp.async (raw f32, cvt in compute);
// B1/B3 via LDG->cvt->STS (tf32 in smem, converted once per element).
// Dynamic smem: 2 x (A 16KB + B1 8KB + B3 8KB) = 64KB.
// ---------------------------------------------------------------------------
#define G13_STAGE_WORDS 8192
#define G13_ITERS (DIM / 32)

__device__ __forceinline__ void g13_cpA(
    uint32_t* sm, int s, int k0, const float* X, int tid, int bm, int tok0)
{
    uint32_t* A = sm + s * G13_STAGE_WORDS;
    #pragma unroll
    for (int i = 0; i < 4; i++) {
        int id  = tid + i * 256;
        int row = id >> 3;
        int c4  = (id & 7) * 4;
        cp16(A + row * 32 + (c4 ^ ((row & 7) * 4)),
             X + (size_t)(tok0 + bm + row) * DIM + k0 + c4);
    }
    CP_COMMIT();
}

__device__ __forceinline__ void g13_ldgB(
    const float* W1, const float* W3, int k0, int tid, int bn,
    float4* b1r, float4* b3r)
{
    #pragma unroll
    for (int i = 0; i < 2; i++) {
        int id  = tid + i * 256;
        int row = id >> 4;
        int c4  = (id & 15) * 4;
        size_t goff = (size_t)(k0 + row) * HID + bn + c4;
        b1r[i] = *(const float4*)(W1 + goff);
        b3r[i] = *(const float4*)(W3 + goff);
    }
}

__device__ __forceinline__ void g13_stsB(
    uint32_t* sm, int s, int tid, const float4* b1r, const float4* b3r)
{
    uint32_t* B1 = sm + s * G13_STAGE_WORDS + 4096;
    uint32_t* B3 = B1 + 2048;
    #pragma unroll
    for (int i = 0; i < 2; i++) {
        int id  = tid + i * 256;
        int row = id >> 4;
        int c4  = (id & 15) * 4;
        int pc  = c4 ^ ((row & 3) * 8);
        uint4 v1 = make_uint4(f2tf32(b1r[i].x), f2tf32(b1r[i].y),
                              f2tf32(b1r[i].z), f2tf32(b1r[i].w));
        uint4 v3 = make_uint4(f2tf32(b3r[i].x), f2tf32(b3r[i].y),
                              f2tf32(b3r[i].z), f2tf32(b3r[i].w));
        *(uint4*)(B1 + row * 64 + pc) = v1;
        *(uint4*)(B3 + row * 64 + pc) = v3;
    }
}

__global__ void __launch_bounds__(256, 2) gemm13_kernel(
    const float* __restrict__ X,
    const float* __restrict__ W1,
    const float* __restrict__ W3,
    int eidx, int tok0)
{
    extern __shared__ __align__(16) uint32_t sm[];

    const int tid  = threadIdx.x;
    const int bm   = blockIdx.y * 128;
    const int bn   = blockIdx.x * 64;
    const int warp = tid >> 5;
    const int lane = tid & 31;
    const int wm   = (warp & 3) * 32;
    const int wn   = (warp >> 2) * 32;
    const int g    = lane >> 2;
    const int tig  = lane & 3;

    float accA[2][4][4];
    float accB[2][4][4];
    #pragma unroll
    for (int mt = 0; mt < 2; mt++)
        #pragma unroll
        for (int nt = 0; nt < 4; nt++)
            #pragma unroll
            for (int i = 0; i < 4; i++) { accA[mt][nt][i] = 0.f; accB[mt][nt][i] = 0.f; }

    float4 b1r[2], b3r[2];
    g13_cpA(sm, 0, 0, X, tid, bm, tok0);
    g13_ldgB(W1, W3, 0, tid, bn, b1r, b3r);
    g13_stsB(sm, 0, tid, b1r, b3r);

    for (int it = 0; it < G13_ITERS; it++) {
        CP_WAIT0();
        __syncthreads();
        int s = it & 1;
        bool pf = (it + 1 < G13_ITERS);
        if (pf) {
            g13_cpA(sm, s ^ 1, (it + 1) * 32, X, tid, bm, tok0);
            g13_ldgB(W1, W3, (it + 1) * 32, tid, bn, b1r, b3r);
        }

        const uint32_t* A  = sm + s * G13_STAGE_WORDS;
        const uint32_t* B1 = A + 4096;
        const uint32_t* B3 = A + 6144;

        #pragma unroll
        for (int kk = 0; kk < 32; kk += 8) {
            uint32_t a[2][4];
            const int xo = 4 * g;
            #pragma unroll
            for (int mt = 0; mt < 2; mt++) {
                int r = wm + mt * 16 + g;
                a[mt][0] = b2tf32(A[(size_t)r * 32 + ((kk + tig) ^ xo)]);
                a[mt][1] = b2tf32(A[(size_t)(r + 8) * 32 + ((kk + tig) ^ xo)]);
                a[mt][2] = b2tf32(A[(size_t)r * 32 + ((kk + tig + 4) ^ xo)]);
                a[mt][3] = b2tf32(A[(size_t)(r + 8) * 32 + ((kk + tig + 4) ^ xo)]);
            }
            const int krow = kk + tig;
            const int ko   = (krow & 3) * 8;
            #pragma unroll
            for (int nt = 0; nt < 4; nt++) {
                int n  = wn + nt * 8 + g;
                int pc = n ^ ko;
                uint32_t b1a = B1[krow * 64 + pc];
                uint32_t b1b = B1[(krow + 4) * 64 + pc];
                uint32_t b3a = B3[krow * 64 + pc];
                uint32_t b3b = B3[(krow + 4) * 64 + pc];
                #pragma unroll
                for (int mt = 0; mt < 2; mt++) {
                    mma8(accA[mt][nt], a[mt][0], a[mt][1], a[mt][2], a[mt][3], b1a, b1b);
                    mma8(accB[mt][nt], a[mt][0], a[mt][1], a[mt][2], a[mt][3], b3a, b3b);
                }
            }
        }

        if (pf) g13_stsB(sm, s ^ 1, tid, b1r, b3r);
    }

    // epilogue: G = tf32(cw * silu(A) * B)
    #pragma unroll
    for (int mt = 0; mt < 2; mt++) {
        int r0 = bm + wm + mt * 16 + g;
        int r1 = r0 + 8;
        float cw0 = g_cw[(tok0 + r0) * 4 + eidx];
        float cw1 = g_cw[(tok0 + r1) * 4 + eidx];
        #pragma unroll
        for (int nt = 0; nt < 4; nt++) {
            int c = bn + wn + nt * 8 + 2 * tig;
            float v00 = silu_f(accA[mt][nt][0]) * accB[mt][nt][0] * cw0;
            float v01 = silu_f(accA[mt][nt][1]) * accB[mt][nt][1] * cw0;
            float v10 = silu_f(accA[mt][nt][2]) * accB[mt][nt][2] * cw1;
            float v11 = silu_f(accA[mt][nt][3]) * accB[mt][nt][3] * cw1;
            uint2 s0 = make_uint2(f2tf32(v00), f2tf32(v01));
            uint2 s1 = make_uint2(f2tf32(v10), f2tf32(v11));
            *(uint2*)&g_G[(size_t)r0 * HID + c] = s0;
            *(uint2*)&g_G[(size_t)r1 * HID + c] = s1;
        }
    }
}

// ---------------------------------------------------------------------------
// GEMM2: out[tok0+t,d] (+)= (G @ W2)[t,d]
// BM=64, BN=64, BK=32; 128 thr, 4 warps of 32x32 (16 mma / 16 LDS per kk).
// A (g_G, already tf32) via cp.async; B (W2) via LDG->cvt->STS.
// Static smem: 2 x (A 8KB + B 8KB) = 32KB. Grid 16x16 = 256 CTAs.
// ---------------------------------------------------------------------------
#define G2_STAGE_WORDS 4096
#define G2_ITERS (HID / 32)

__device__ __forceinline__ void g2_cpA(
    uint32_t* smb, int s, int k0, int tid, int bm)
{
    uint32_t* A = smb + s * G2_STAGE_WORDS;
    #pragma unroll
    for (int i = 0; i < 4; i++) {
        int id  = tid + i * 128;
        int row = id >> 3;
        int c4  = (id & 7) * 4;
        cp16(A + row * 32 + (c4 ^ ((row & 7) * 4)),
             g_G + (size_t)(bm + row) * HID + k0 + c4);
    }
    CP_COMMIT();
}

__device__ __forceinline__ void g2_ldgB(
    const float* W2, int k0, int tid, int bn, float4* br)
{
    #pragma unroll
    for (int i = 0; i < 4; i++) {
        int id  = tid + i * 128;
        int row = id >> 4;
        int c4  = (id & 15) * 4;
        br[i] = *(const float4*)(W2 + (size_t)(k0 + row) * DIM + bn + c4);
    }
}

__device__ __forceinline__ void g2_stsB(
    uint32_t* smb, int s, int tid, const float4* br)
{
    uint32_t* B = smb + s * G2_STAGE_WORDS + 2048;
    #pragma unroll
    for (int i = 0; i < 4; i++) {
        int id  = tid + i * 128;
        int row = id >> 4;
        int c4  = (id & 15) * 4;
        int pc  = c4 ^ ((row & 3) * 8);
        uint4 v = make_uint4(f2tf32(br[i].x), f2tf32(br[i].y),
                             f2tf32(br[i].z), f2tf32(br[i].w));
        *(uint4*)(B + row * 64 + pc) = v;
    }
}

__global__ void __launch_bounds__(128, 4) gemm2_kernel(
    const float* __restrict__ W2,
    float* __restrict__ out,
    int first, int tok0)
{
    __shared__ __align__(16) uint32_t sm2[2 * G2_STAGE_WORDS];

    const int tid  = threadIdx.x;
    const int bm   = blockIdx.y * 64;
    const int bn   = blockIdx.x * 64;
    const int warp = tid >> 5;
    const int lane = tid & 31;
    const int wm   = (warp & 1) * 32;
    const int wn   = (warp >> 1) * 32;
    const int g    = lane >> 2;
    const int tig  = lane & 3;

    float acc[2][4][4];
    #pragma unroll
    for (int mt = 0; mt < 2; mt++)
        #pragma unroll
        for (int nt = 0; nt < 4; nt++)
            #pragma unroll
            for (int i = 0; i < 4; i++) acc[mt][nt][i] = 0.f;

    float4 br[4];
    g2_cpA(sm2, 0, 0, tid, bm);
    g2_ldgB(W2, 0, tid, bn, br);
    g2_stsB(sm2, 0, tid, br);

    for (int it = 0; it < G2_ITERS; it++) {
        CP_WAIT0();
        __syncthreads();
        int s = it & 1;
        bool pf = (it + 1 < G2_ITERS);
        if (pf) {
            g2_cpA(sm2, s ^ 1, (it + 1) * 32, tid, bm);
            g2_ldgB(W2, (it + 1) * 32, tid, bn, br);
        }

        const uint32_t* A = sm2 + s * G2_STAGE_WORDS;
        const uint32_t* B = A + 2048;

        #pragma unroll
        for (int kk = 0; kk < 32; kk += 8) {
            uint32_t a[2][4];
            const int xo = 4 * g;
            #pragma unroll
            for (int mt = 0; mt < 2; mt++) {
                int r = wm + mt * 16 + g;
                a[mt][0] = A[(size_t)r * 32 + ((kk + tig) ^ xo)];
                a[mt][1] = A[(size_t)(r + 8) * 32 + ((kk + tig) ^ xo)];
                a[mt][2] = A[(size_t)r * 32 + ((kk + tig + 4) ^ xo)];
                a[mt][3] = A[(size_t)(r + 8) * 32 + ((kk + tig + 4) ^ xo)];
            }
            const int krow = kk + tig;
            const int ko   = (krow & 3) * 8;
            #pragma unroll
            for (int nt = 0; nt < 4; nt++) {
                int n  = wn + nt * 8 + g;
                int pc = n ^ ko;
                uint32_t b0 = B[krow * 64 + pc];
                uint32_t b1 = B[(krow + 4) * 64 + pc];
                #pragma unroll
                for (int mt = 0; mt < 2; mt++)
                    mma8(acc[mt][nt], a[mt][0], a[mt][1], a[mt][2], a[mt][3], b0, b1);
            }
        }

        if (pf) g2_stsB(sm2, s ^ 1, tid, br);
    }

    // epilogue: accumulate into out
    #pragma unroll
    for (int mt = 0; mt < 2; mt++) {
        int r0 = tok0 + bm + wm + mt * 16 + g;
        int r1 = r0 + 8;
        #pragma unroll
        for (int nt = 0; nt < 4; nt++) {
            int c = bn + wn + nt * 8 + 2 * tig;
            float2* p0 = (float2*)&out[(size_t)r0 * DIM + c];
            float2* p1 = (float2*)&out[(size_t)r1 * DIM + c];
            float2 v0 = make_float2(acc[mt][nt][0], acc[mt][nt][1]);
            float2 v1 = make_float2(acc[mt][nt][2], acc[mt][nt][3]);
            if (!first) {
                float2 o0 = *p0; v0.x += o0.x; v0.y += o0.y;
                float2 o1 = *p1; v1.x += o1.x; v1.y += o1.y;
            }
            *p0 = v0;
            *p1 = v1;
        }
    }
}

// ---------------------------------------------------------------------------
extern "C" void kernel_launch(void* const* d_in, const int* in_sizes, int n_in,
                              void* d_out, int out_size) {
    const float* x   = (const float*)d_in[0];  // [2,2048,1024]
    const float* gw  = (const float*)d_in[1];  // [8,1024]
    const float* w1  = (const float*)d_in[2];  // [8,1024,5632]
    const float* w2  = (const float*)d_in[3];  // [8,5632,1024]
    const float* w3  = (const float*)d_in[4];  // [8,1024,5632]
    float* out = (float*)d_out;                // [2,2048,1024]

    cudaFuncSetAttribute(gemm13_kernel,
                         cudaFuncAttributeMaxDynamicSharedMemorySize, 65536);

    gate_kernel<<<T_TOK / 4, 128>>>(x, gw);

    for (int e = 0; e < EACT; e++) {
        const float* w1e = w1 + (size_t)e * DIM * HID;
        const float* w3e = w3 + (size_t)e * DIM * HID;
        const float* w2e = w2 + (size_t)e * HID * DIM;
        for (int tb = 0; tb < T_TOK / TB; tb++) {
            int tok0 = tb * TB;
            gemm13_kernel<<<dim3(HID / 64, TB / 128), 256, 65536>>>(x, w1e, w3e, e, tok0);
            gemm2_kernel<<<dim3(DIM / 64, TB / 64), 128>>>(w2e, out, e == 0, tok0);
        }
    }
}

// round 8
// speedup vs baseline: 1.2990x; 1.2990x over previous
#include <cuda_runtime.h>
#include <cstdint>

// Problem constants
#define T_TOK 4096
#define DIM   1024
#define HID   5632
#define EACT  4
#define TB    1024   // token block
#define NTB   (T_TOK / TB)

// Scratch: combine weights, routing lists, intermediate G (tf32 bits, compacted)
__device__ float g_cw[T_TOK * EACT];
__device__ int   g_route[EACT * NTB * TB];
__device__ int   g_cnt[EACT * NTB];
__device__ __align__(16) uint32_t g_G[(size_t)TB * HID];

__device__ __forceinline__ uint32_t f2tf32(float f) {
    uint32_t r;
    asm("cvt.rna.tf32.f32 %0, %1;" : "=r"(r) : "f"(f));
    return r;
}
__device__ __forceinline__ uint32_t b2tf32(uint32_t b) {
    return f2tf32(__uint_as_float(b));
}

__device__ __forceinline__ void cp16(uint32_t* smem_ptr, const void* gptr) {
    uint32_t a = (uint32_t)__cvta_generic_to_shared(smem_ptr);
    asm volatile("cp.async.cg.shared.global [%0], [%1], 16;" :: "r"(a), "l"(gptr));
}
#define CP_COMMIT() asm volatile("cp.async.commit_group;")
#define CP_WAIT0()  asm volatile("cp.async.wait_group 0;")

__device__ __forceinline__ void mma8(float* c,
                                     uint32_t a0, uint32_t a1, uint32_t a2, uint32_t a3,
                                     uint32_t b0, uint32_t b1) {
    asm volatile(
        "mma.sync.aligned.m16n8k8.row.col.f32.tf32.tf32.f32 "
        "{%0,%1,%2,%3}, {%4,%5,%6,%7}, {%8,%9}, {%0,%1,%2,%3};\n"
        : "+f"(c[0]), "+f"(c[1]), "+f"(c[2]), "+f"(c[3])
        : "r"(a0), "r"(a1), "r"(a2), "r"(a3), "r"(b0), "r"(b1));
}

__device__ __forceinline__ float silu_f(float v) {
    return v / (1.0f + __expf(-v));
}

// ---------------------------------------------------------------------------
// Zero output (harness poisons d_out).
// ---------------------------------------------------------------------------
__global__ void zero_out_kernel(float4* out) {
    out[blockIdx.x * 256 + threadIdx.x] = make_float4(0.f, 0.f, 0.f, 0.f);
}

// ---------------------------------------------------------------------------
// Gate: one warp per token; experts 4..7 masked. softmax->top2->renorm ==
// softmax over the two best logits.
// ---------------------------------------------------------------------------
__global__ void gate_kernel(const float* __restrict__ x,
                            const float* __restrict__ gw) {
    int warp = (blockIdx.x * blockDim.x + threadIdx.x) >> 5;
    int lane = threadIdx.x & 31;
    if (warp >= T_TOK) return;

    const float* xr = x + (size_t)warp * DIM;
    float p0 = 0.f, p1 = 0.f, p2 = 0.f, p3 = 0.f;
    for (int d = lane; d < DIM; d += 32) {
        float xv = xr[d];
        p0 += xv * gw[0 * DIM + d];
        p1 += xv * gw[1 * DIM + d];
        p2 += xv * gw[2 * DIM + d];
        p3 += xv * gw[3 * DIM + d];
    }
    #pragma unroll
    for (int off = 16; off; off >>= 1) {
        p0 += __shfl_down_sync(0xffffffff, p0, off);
        p1 += __shfl_down_sync(0xffffffff, p1, off);
        p2 += __shfl_down_sync(0xffffffff, p2, off);
        p3 += __shfl_down_sync(0xffffffff, p3, off);
    }
    if (lane == 0) {
        float l[4] = {p0, p1, p2, p3};
        int i0 = 0;
        #pragma unroll
        for (int e = 1; e < 4; e++) if (l[e] > l[i0]) i0 = e;
        int i1 = -1;
        #pragma unroll
        for (int e = 0; e < 4; e++) {
            if (e == i0) continue;
            if (i1 < 0 || l[e] > l[i1]) i1 = e;
        }
        float w0 = 1.0f / (1.0f + __expf(l[i1] - l[i0]));
        float w1 = 1.0f - w0;
        float* cwr = g_cw + warp * 4;
        cwr[0] = 0.f; cwr[1] = 0.f; cwr[2] = 0.f; cwr[3] = 0.f;
        cwr[i0] = w0;
        cwr[i1] = w1;
    }
}

// ---------------------------------------------------------------------------
// Routing: per (expert, token-block) compact the selected tokens.
// 16 blocks x 256 threads; deterministic block-scan (token order preserved).
// ---------------------------------------------------------------------------
__global__ void route_kernel() {
    const int e   = blockIdx.x >> 2;
    const int tb  = blockIdx.x & 3;
    const int tid = threadIdx.x;
    const int t0  = tb * TB;

    int flags[4];
    int myc = 0;
    #pragma unroll
    for (int j = 0; j < 4; j++) {
        int t = t0 + tid * 4 + j;
        int f = (g_cw[t * 4 + e] > 0.f) ? 1 : 0;
        flags[j] = f;
        myc += f;
    }

    __shared__ int sc[256];
    sc[tid] = myc;
    __syncthreads();
    #pragma unroll
    for (int off = 1; off < 256; off <<= 1) {
        int v = (tid >= off) ? sc[tid - off] : 0;
        __syncthreads();
        sc[tid] += v;
        __syncthreads();
    }
    int pos = sc[tid] - myc;   // exclusive prefix

    int* lst = g_route + (e * NTB + tb) * TB;
    #pragma unroll
    for (int j = 0; j < 4; j++) {
        if (flags[j]) lst[pos++] = t0 + tid * 4 + j;
    }
    if (tid == 255) g_cnt[e * NTB + tb] = sc[255];
}

// ---------------------------------------------------------------------------
// GEMM13 (routed): for slots s < cnt[e][tb], token t = route[s]:
// G[s,h] = tf32( cw[t,e] * silu(X[t]@W1)[h] * (X[t]@W3)[h] )
// BM=128, BN=64, BK=32; 2-stage cp.async; XOR-swizzled smem.
// Dynamic smem: 2 x (A 16KB + B1 8KB + B3 8KB) = 64KB.
// ---------------------------------------------------------------------------
#define G13_STAGE_WORDS 8192
#define G13_ITERS (DIM / 32)

__device__ __forceinline__ void g13_load_stage(
    uint32_t* sm, const int* toks, int s, int k0,
    const float* X, const float* W1, const float* W3,
    int tid, int bn)
{
    uint32_t* A  = sm + s * G13_STAGE_WORDS;
    uint32_t* B1 = A + 4096;
    uint32_t* B3 = A + 6144;
    #pragma unroll
    for (int i = 0; i < 4; i++) {
        int id  = tid + i * 256;
        int row = id >> 3;
        int c4  = (id & 7) * 4;
        cp16(A + row * 32 + (c4 ^ ((row & 7) * 4)),
             X + (size_t)toks[row] * DIM + k0 + c4);
    }
    #pragma unroll
    for (int i = 0; i < 2; i++) {
        int id  = tid + i * 256;
        int row = id >> 4;
        int c4  = (id & 15) * 4;
        int pc  = c4 ^ ((row & 3) * 8);
        size_t goff = (size_t)(k0 + row) * HID + bn + c4;
        cp16(B1 + row * 64 + pc, W1 + goff);
        cp16(B3 + row * 64 + pc, W3 + goff);
    }
    CP_COMMIT();
}

__global__ void __launch_bounds__(256, 2) gemm13_kernel(
    const float* __restrict__ X,
    const float* __restrict__ W1,
    const float* __restrict__ W3,
    int eidx, int tb)
{
    const int cnt = g_cnt[eidx * NTB + tb];
    const int bm  = blockIdx.y * 128;
    if (bm >= cnt) return;

    extern __shared__ __align__(16) uint32_t sm[];
    __shared__ int toks[128];

    const int tid  = threadIdx.x;
    const int bn   = blockIdx.x * 64;
    const int warp = tid >> 5;
    const int lane = tid & 31;
    const int wm   = (warp & 3) * 32;
    const int wn   = (warp >> 2) * 32;
    const int g    = lane >> 2;
    const int tig  = lane & 3;

    if (tid < 128) {
        int slot = bm + tid;
        if (slot >= cnt) slot = cnt - 1;
        toks[tid] = g_route[(eidx * NTB + tb) * TB + slot];
    }
    __syncthreads();

    float accA[2][4][4];
    float accB[2][4][4];
    #pragma unroll
    for (int mt = 0; mt < 2; mt++)
        #pragma unroll
        for (int nt = 0; nt < 4; nt++)
            #pragma unroll
            for (int i = 0; i < 4; i++) { accA[mt][nt][i] = 0.f; accB[mt][nt][i] = 0.f; }

    g13_load_stage(sm, toks, 0, 0, X, W1, W3, tid, bn);

    for (int it = 0; it < G13_ITERS; it++) {
        CP_WAIT0();
        __syncthreads();
        int s = it & 1;
        if (it + 1 < G13_ITERS)
            g13_load_stage(sm, toks, s ^ 1, (it + 1) * 32, X, W1, W3, tid, bn);

        const uint32_t* A  = sm + s * G13_STAGE_WORDS;
        const uint32_t* B1 = A + 4096;
        const uint32_t* B3 = A + 6144;

        #pragma unroll
        for (int kk = 0; kk < 32; kk += 8) {
            uint32_t a[2][4];
            const int xo = 4 * g;
            #pragma unroll
            for (int mt = 0; mt < 2; mt++) {
                int r = wm + mt * 16 + g;
                a[mt][0] = b2tf32(A[(size_t)r * 32 + ((kk + tig) ^ xo)]);
                a[mt][1] = b2tf32(A[(size_t)(r + 8) * 32 + ((kk + tig) ^ xo)]);
                a[mt][2] = b2tf32(A[(size_t)r * 32 + ((kk + tig + 4) ^ xo)]);
                a[mt][3] = b2tf32(A[(size_t)(r + 8) * 32 + ((kk + tig + 4) ^ xo)]);
            }
            const int krow = kk + tig;
            const int ko   = (krow & 3) * 8;
            #pragma unroll
            for (int nt = 0; nt < 4; nt++) {
                int n  = wn + nt * 8 + g;
                int pc = n ^ ko;
                uint32_t b1a = b2tf32(B1[krow * 64 + pc]);
                uint32_t b1b = b2tf32(B1[(krow + 4) * 64 + pc]);
                uint32_t b3a = b2tf32(B3[krow * 64 + pc]);
                uint32_t b3b = b2tf32(B3[(krow + 4) * 64 + pc]);
                #pragma unroll
                for (int mt = 0; mt < 2; mt++) {
                    mma8(accA[mt][nt], a[mt][0], a[mt][1], a[mt][2], a[mt][3], b1a, b1b);
                    mma8(accB[mt][nt], a[mt][0], a[mt][1], a[mt][2], a[mt][3], b3a, b3b);
                }
            }
        }
    }

    // epilogue: G[slot] = tf32(cw * silu(A) * B)   (rows >= cnt: junk, unread)
    #pragma unroll
    for (int mt = 0; mt < 2; mt++) {
        int lr0 = wm + mt * 16 + g;
        int lr1 = lr0 + 8;
        float cw0 = g_cw[toks[lr0] * 4 + eidx];
        float cw1 = g_cw[toks[lr1] * 4 + eidx];
        size_t r0 = (size_t)(bm + lr0) * HID;
        size_t r1 = (size_t)(bm + lr1) * HID;
        #pragma unroll
        for (int nt = 0; nt < 4; nt++) {
            int c = bn + wn + nt * 8 + 2 * tig;
            float v00 = silu_f(accA[mt][nt][0]) * accB[mt][nt][0] * cw0;
            float v01 = silu_f(accA[mt][nt][1]) * accB[mt][nt][1] * cw0;
            float v10 = silu_f(accA[mt][nt][2]) * accB[mt][nt][2] * cw1;
            float v11 = silu_f(accA[mt][nt][3]) * accB[mt][nt][3] * cw1;
            *(uint2*)&g_G[r0 + c] = make_uint2(f2tf32(v00), f2tf32(v01));
            *(uint2*)&g_G[r1 + c] = make_uint2(f2tf32(v10), f2tf32(v11));
        }
    }
}

// ---------------------------------------------------------------------------
// GEMM2 (routed): out[route[s],d] += (G[s,:] @ W2)[d] for s < cnt.
// BM=64, BN=64, BK=32; 256 thr (8 warps, 32x16 tile); 2-stage cp.async.
// Static smem: 2 x (A 8KB + B 8KB) = 32KB.
// ---------------------------------------------------------------------------
#define G2_STAGE_WORDS 4096
#define G2_ITERS (HID / 32)

__device__ __forceinline__ void g2_load_stage(
    uint32_t* smb, int s, int k0,
    const float* W2, int tid, int bm, int bn)
{
    uint32_t* A = smb + s * G2_STAGE_WORDS;
    uint32_t* B = A + 2048;
    #pragma unroll
    for (int i = 0; i < 2; i++) {
        int id  = tid + i * 256;
        int row = id >> 3;
        int c4  = (id & 7) * 4;
        cp16(A + row * 32 + (c4 ^ ((row & 7) * 4)),
             g_G + (size_t)(bm + row) * HID + k0 + c4);
    }
    #pragma unroll
    for (int i = 0; i < 2; i++) {
        int id  = tid + i * 256;
        int row = id >> 4;
        int c4  = (id & 15) * 4;
        cp16(B + row * 64 + (c4 ^ ((row & 3) * 8)),
             W2 + (size_t)(k0 + row) * DIM + bn + c4);
    }
    CP_COMMIT();
}

__global__ void __launch_bounds__(256) gemm2_kernel(
    const float* __restrict__ W2,
    float* __restrict__ out,
    int eidx, int tb)
{
    const int cnt = g_cnt[eidx * NTB + tb];
    const int bm  = blockIdx.y * 64;
    if (bm >= cnt) return;

    __shared__ __align__(16) uint32_t sm2[2 * G2_STAGE_WORDS];

    const int tid  = threadIdx.x;
    const int bn   = blockIdx.x * 64;
    const int warp = tid >> 5;
    const int lane = tid & 31;
    const int wm   = (warp & 1) * 32;
    const int wn   = (warp >> 1) * 16;
    const int g    = lane >> 2;
    const int tig  = lane & 3;

    float acc[2][2][4];
    #pragma unroll
    for (int mt = 0; mt < 2; mt++)
        #pragma unroll
        for (int nt = 0; nt < 2; nt++)
            #pragma unroll
            for (int i = 0; i < 4; i++) acc[mt][nt][i] = 0.f;

    g2_load_stage(sm2, 0, 0, W2, tid, bm, bn);

    for (int it = 0; it < G2_ITERS; it++) {
        CP_WAIT0();
        __syncthreads();
        int s = it & 1;
        if (it + 1 < G2_ITERS)
            g2_load_stage(sm2, s ^ 1, (it + 1) * 32, W2, tid, bm, bn);

        const uint32_t* A = sm2 + s * G2_STAGE_WORDS;
        const uint32_t* B = A + 2048;

        #pragma unroll
        for (int kk = 0; kk < 32; kk += 8) {
            uint32_t a[2][4];
            const int xo = 4 * g;
            #pragma unroll
            for (int mt = 0; mt < 2; mt++) {
                int r = wm + mt * 16 + g;
                a[mt][0] = A[(size_t)r * 32 + ((kk + tig) ^ xo)];
                a[mt][1] = A[(size_t)(r + 8) * 32 + ((kk + tig) ^ xo)];
                a[mt][2] = A[(size_t)r * 32 + ((kk + tig + 4) ^ xo)];
                a[mt][3] = A[(size_t)(r + 8) * 32 + ((kk + tig + 4) ^ xo)];
            }
            const int krow = kk + tig;
            const int ko   = (krow & 3) * 8;
            #pragma unroll
            for (int nt = 0; nt < 2; nt++) {
                int n  = wn + nt * 8 + g;
                int pc = n ^ ko;
                uint32_t b0 = b2tf32(B[krow * 64 + pc]);
                uint32_t b1 = b2tf32(B[(krow + 4) * 64 + pc]);
                #pragma unroll
                for (int mt = 0; mt < 2; mt++)
                    mma8(acc[mt][nt], a[mt][0], a[mt][1], a[mt][2], a[mt][3], b0, b1);
            }
        }
    }

    // epilogue: scatter-accumulate into out (guard rows >= cnt)
    const int* lst = g_route + (eidx * NTB + tb) * TB;
    #pragma unroll
    for (int mt = 0; mt < 2; mt++) {
        int lr0 = wm + mt * 16 + g;
        int lr1 = lr0 + 8;
        int s0 = bm + lr0;
        int s1 = bm + lr1;
        bool v0ok = s0 < cnt;
        bool v1ok = s1 < cnt;
        int t0 = v0ok ? lst[s0] : 0;
        int t1 = v1ok ? lst[s1] : 0;
        #pragma unroll
        for (int nt = 0; nt < 2; nt++) {
            int c = bn + wn + nt * 8 + 2 * tig;
            if (v0ok) {
                float2* p = (float2*)&out[(size_t)t0 * DIM + c];
                float2 o = *p;
                o.x += acc[mt][nt][0];
                o.y += acc[mt][nt][1];
                *p = o;
            }
            if (v1ok) {
                float2* p = (float2*)&out[(size_t)t1 * DIM + c];
                float2 o = *p;
                o.x += acc[mt][nt][2];
                o.y += acc[mt][nt][3];
                *p = o;
            }
        }
    }
}

// ---------------------------------------------------------------------------
extern "C" void kernel_launch(void* const* d_in, const int* in_sizes, int n_in,
                              void* d_out, int out_size) {
    const float* x   = (const float*)d_in[0];  // [2,2048,1024]
    const float* gw  = (const float*)d_in[1];  // [8,1024]
    const float* w1  = (const float*)d_in[2];  // [8,1024,5632]
    const float* w2  = (const float*)d_in[3];  // [8,5632,1024]
    const float* w3  = (const float*)d_in[4];  // [8,1024,5632]
    float* out = (float*)d_out;                // [2,2048,1024]

    cudaFuncSetAttribute(gemm13_kernel,
                         cudaFuncAttributeMaxDynamicSharedMemorySize, 65536);

    zero_out_kernel<<<(T_TOK * DIM) / (256 * 4), 256>>>((float4*)out);
    gate_kernel<<<T_TOK / 4, 128>>>(x, gw);
    route_kernel<<<EACT * NTB, 256>>>();

    for (int e = 0; e < EACT; e++) {
        const float* w1e = w1 + (size_t)e * DIM * HID;
        const float* w3e = w3 + (size_t)e * DIM * HID;
        const float* w2e = w2 + (size_t)e * HID * DIM;
        for (int tb = 0; tb < NTB; tb++) {
            gemm13_kernel<<<dim3(HID / 64, TB / 128), 256, 65536>>>(x, w1e, w3e, e, tb);
            gemm2_kernel<<<dim3(DIM / 64, TB / 64), 256>>>(w2e, out, e, tb);
        }
    }
}